// round 1
// baseline (speedup 1.0000x reference)
#include <cuda_runtime.h>
#include <math.h>

#define BB 2
#define CC 48
#define HH 48
#define TT 400
#define FF 129
#define WW 11
#define FP 133            // padded tile row stride (odd -> conflict-free columns)
#define OC 96             // 2*C fusion output channels
#define NTHREADS 256

#define TILE_ELEMS (CC*FP)          // 6384 floats per 48x129 tile (padded)

// ---------------- device scratch (no allocations allowed) ----------------
__device__ float g_w1f[HH*CC], g_b1f[HH];
__device__ float g_w2f[HH*HH], g_b2f[HH];
__device__ float g_w3f[HH*CC], g_b3f[HH];
__device__ float g_wff[OC*OC], g_bff[OC];
__device__ float g_kref[BB*HH*TT*FF];   // precomputed K_ref (B,H,T,F)

// ---------------- setup: fold dw into pw, BN into fusion ----------------
__global__ void setup_kernel(const float* pw1_w, const float* pw1_b,
                             const float* dw1_w, const float* dw1_b,
                             const float* pw2_w, const float* pw2_b,
                             const float* dw2_w, const float* dw2_b,
                             const float* pw3_w, const float* pw3_b,
                             const float* dw3_w, const float* dw3_b,
                             const float* fusion_w, const float* fusion_b,
                             const float* bn_gamma, const float* bn_beta,
                             const float* bn_mean, const float* bn_var)
{
    int tid = threadIdx.x;
    for (int i = tid; i < HH*CC; i += blockDim.x) {
        int c = i % CC;
        g_w1f[i] = pw1_w[i] * dw1_w[c];
        g_w2f[i] = pw2_w[i] * dw2_w[c];
        g_w3f[i] = pw3_w[i] * dw3_w[c];
    }
    if (tid < HH) {
        float s1 = pw1_b[tid], s2 = pw2_b[tid], s3 = pw3_b[tid];
        for (int c = 0; c < CC; c++) {
            s1 += pw1_w[tid*CC + c] * dw1_b[c];
            s2 += pw2_w[tid*CC + c] * dw2_b[c];
            s3 += pw3_w[tid*CC + c] * dw3_b[c];
        }
        g_b1f[tid] = s1; g_b2f[tid] = s2; g_b3f[tid] = s3;
    }
    for (int i = tid; i < OC*OC; i += blockDim.x) {
        int o = i / OC;
        float s = bn_gamma[o] * rsqrtf(bn_var[o] + 1e-5f);
        g_wff[i] = fusion_w[i] * s;
    }
    if (tid < OC) {
        float s = bn_gamma[tid] * rsqrtf(bn_var[tid] + 1e-5f);
        g_bff[tid] = (fusion_b[tid] - bn_mean[tid]) * s + bn_beta[tid];
    }
}

// ---------------- K_ref precompute: one block per (b,t) ----------------
__global__ void kref_kernel(const float* __restrict__ x_ref)
{
    extern __shared__ float sm[];
    float* xr = sm;                  // CC*FP
    float* w3 = xr + TILE_ELEMS;     // HH*CC
    float* b3 = w3 + HH*CC;          // HH

    int b = blockIdx.x / TT;
    int t = blockIdx.x % TT;
    int tid = threadIdx.x;

    for (int i = tid; i < CC*FF; i += NTHREADS) {
        int c = i / FF, f = i % FF;
        xr[c*FP + f] = x_ref[((b*CC + c)*TT + t)*FF + f];
    }
    for (int i = tid; i < HH*CC; i += NTHREADS) w3[i] = g_w3f[i];
    if (tid < HH) b3[tid] = g_b3f[tid];
    __syncthreads();

    for (int i = tid; i < HH*FF; i += NTHREADS) {
        int h = i / FF, f = i % FF;
        float acc = b3[h];
        #pragma unroll 8
        for (int c = 0; c < CC; c++) acc += w3[h*CC + c] * xr[c*FP + f];
        g_kref[((b*HH + h)*TT + t)*FF + f] = acc;
    }
}

// ---------------- main fused kernel: one block per (b,t) ----------------
__global__ void main_kernel(const float* __restrict__ x_mic,
                            const float* __restrict__ x_ref,
                            const float* __restrict__ prelu_a,
                            float* __restrict__ out,
                            int write_mic)
{
    extern __shared__ float sm[];
    float* xm   = sm;                       // tile: x_mic, later x_ref window slice
    float* Qs   = xm   + TILE_ELEMS;
    float* Ks   = Qs   + TILE_ELEMS;        // K, later K_ref window slice
    float* mic  = Ks   + TILE_ELEMS;
    float* refb = mic  + TILE_ELEMS;
    float* w1   = refb + TILE_ELEMS;        // HH*CC
    float* w2   = w1   + HH*CC;             // HH*HH
    float* wf   = w2   + HH*HH;             // OC*OC
    float* b1   = wf   + OC*OC;             // HH
    float* b2   = b1   + HH;                // HH
    float* bf   = b2   + HH;                // OC
    float* arow = bf   + OC;                // 8 warps * 132

    int b = blockIdx.x / TT;
    int t = blockIdx.x % TT;
    int tid  = threadIdx.x;
    int warp = tid >> 5;
    int lane = tid & 31;

    // ---- loads ----
    for (int i = tid; i < CC*FF; i += NTHREADS) {
        int c = i / FF, f = i % FF;
        xm[c*FP + f] = x_mic[((b*CC + c)*TT + t)*FF + f];
    }
    for (int i = tid; i < HH*CC; i += NTHREADS) w1[i] = g_w1f[i];
    for (int i = tid; i < HH*HH; i += NTHREADS) w2[i] = g_w2f[i];
    for (int i = tid; i < OC*OC; i += NTHREADS) wf[i] = g_wff[i];
    if (tid < HH) { b1[tid] = g_b1f[tid]; b2[tid] = g_b2f[tid]; }
    if (tid < OC) bf[tid] = g_bff[tid];
    for (int i = tid; i < TILE_ELEMS; i += NTHREADS) refb[i] = 0.f;
    __syncthreads();

    // ---- Q = W1f @ xm + b1f ----
    for (int i = tid; i < HH*FF; i += NTHREADS) {
        int h = i / FF, f = i % FF;
        float acc = b1[h];
        #pragma unroll 8
        for (int c = 0; c < CC; c++) acc += w1[h*CC + c] * xm[c*FP + f];
        Qs[h*FP + f] = acc;
    }
    __syncthreads();

    // ---- K = W2f @ Q + b2f ----
    for (int i = tid; i < HH*FF; i += NTHREADS) {
        int h = i / FF, f = i % FF;
        float acc = b2[h];
        #pragma unroll 8
        for (int c = 0; c < CC; c++) acc += w2[h*CC + c] * Qs[c*FP + f];
        Ks[h*FP + f] = acc;
    }
    __syncthreads();

    // ---- scores + softmax over g + mic_out, streamed per f (warp per f) ----
    const float scale = 0.144337567297406441f;   // 1/sqrt(48)
    for (int f = warp; f < FF; f += 8) {
        float s0 = 0.f, s1 = 0.f, s2 = 0.f, s3 = 0.f, s4 = 0.f;
        #pragma unroll 4
        for (int h = 0; h < HH; h++) {
            float q = Qs[h*FP + f];
            const float* kr = Ks + h*FP;
            s0 += q * kr[lane];
            s1 += q * kr[lane + 32];
            s2 += q * kr[lane + 64];
            s3 += q * kr[lane + 96];
            s4 += q * kr[128];          // broadcast; g=128 (same in every lane)
        }
        s0 *= scale; s1 *= scale; s2 *= scale; s3 *= scale; s4 *= scale;
        float m = fmaxf(fmaxf(s0, s1), fmaxf(s2, s3));
        m = fmaxf(m, s4);
        #pragma unroll
        for (int o = 16; o; o >>= 1) m = fmaxf(m, __shfl_xor_sync(0xffffffffu, m, o));
        float e0 = __expf(s0 - m), e1 = __expf(s1 - m), e2 = __expf(s2 - m),
              e3 = __expf(s3 - m), e4 = __expf(s4 - m);
        float ssum = e0 + e1 + e2 + e3 + (lane == 0 ? e4 : 0.f);
        #pragma unroll
        for (int o = 16; o; o >>= 1) ssum += __shfl_xor_sync(0xffffffffu, ssum, o);
        float inv = 1.f / ssum;
        float* ar = arow + warp*132;
        ar[lane]      = e0 * inv;
        ar[lane + 32] = e1 * inv;
        ar[lane + 64] = e2 * inv;
        ar[lane + 96] = e3 * inv;
        if (lane == 0) ar[128] = e4 * inv;
        __syncwarp();
        // mic_out[c][f] = sum_g A[g] * xm[c][g]
        for (int c = lane; c < CC; c += 32) {
            float acc = 0.f;
            #pragma unroll 4
            for (int g = 0; g < FF; g++) acc += ar[g] * xm[c*FP + g];
            mic[c*FP + f] = acc;
        }
        __syncwarp();
    }
    __syncthreads();

    // ---- windowed ref cross-attention (h == c, softmax over F per (h,j)) ----
    for (int j = 0; j < WW; j++) {
        int tj = t + j - (WW - 1);
        if (tj < 0) continue;            // zero-padded Vu -> zero contribution
        for (int i = tid; i < CC*FF; i += NTHREADS) {
            int c = i / FF, f = i % FF;
            xm[c*FP + f] = x_ref[((b*CC + c)*TT + tj)*FF + f];
            Ks[c*FP + f] = g_kref[((b*HH + c)*TT + tj)*FF + f];
        }
        __syncthreads();
        for (int h = warp; h < HH; h += 8) {
            const float* qr = Qs + h*FP;
            const float* kr = Ks + h*FP;
            float p0 = qr[lane]      * kr[lane];
            float p1 = qr[lane + 32] * kr[lane + 32];
            float p2 = qr[lane + 64] * kr[lane + 64];
            float p3 = qr[lane + 96] * kr[lane + 96];
            float p4 = qr[128]       * kr[128];
            float m = fmaxf(fmaxf(p0, p1), fmaxf(p2, p3));
            m = fmaxf(m, p4);
            #pragma unroll
            for (int o = 16; o; o >>= 1) m = fmaxf(m, __shfl_xor_sync(0xffffffffu, m, o));
            float e0 = __expf(p0 - m), e1 = __expf(p1 - m), e2 = __expf(p2 - m),
                  e3 = __expf(p3 - m), e4 = __expf(p4 - m);
            float ssum = e0 + e1 + e2 + e3 + (lane == 0 ? e4 : 0.f);
            #pragma unroll
            for (int o = 16; o; o >>= 1) ssum += __shfl_xor_sync(0xffffffffu, ssum, o);
            float inv = 1.f / ssum;
            float* rb = refb + h*FP;
            const float* vr = xm + h*FP;
            rb[lane]      += vr[lane]      * e0 * inv;
            rb[lane + 32] += vr[lane + 32] * e1 * inv;
            rb[lane + 64] += vr[lane + 64] * e2 * inv;
            rb[lane + 96] += vr[lane + 96] * e3 * inv;
            if (lane == 0) rb[128] += vr[128] * e4 * inv;
        }
        __syncthreads();
    }

    // ---- fusion GEMM (BN folded) + PReLU + writes ----
    float aneg = prelu_a[0];
    for (int i = tid; i < OC*FF; i += NTHREADS) {
        int o = i / FF, f = i % FF;
        float acc = bf[o];
        const float* wo = wf + o*OC;
        #pragma unroll 8
        for (int c = 0; c < CC; c++) acc += wo[c]      * mic[c*FP + f];
        #pragma unroll 8
        for (int c = 0; c < CC; c++) acc += wo[CC + c] * refb[c*FP + f];
        out[((b*OC + o)*TT + t)*FF + f] = (acc >= 0.f) ? acc : aneg * acc;
    }
    if (write_mic) {
        float* out2 = out + (size_t)BB*OC*TT*FF;
        for (int i = tid; i < CC*FF; i += NTHREADS) {
            int c = i / FF, f = i % FF;
            out2[((b*CC + c)*TT + t)*FF + f] = mic[c*FP + f];
        }
    }
}

// ---------------- launch ----------------
extern "C" void kernel_launch(void* const* d_in, const int* in_sizes, int n_in,
                              void* d_out, int out_size)
{
    const float* x_mic    = (const float*)d_in[0];
    const float* x_ref    = (const float*)d_in[1];
    const float* dw1_w    = (const float*)d_in[2];
    const float* dw1_b    = (const float*)d_in[3];
    const float* pw1_w    = (const float*)d_in[4];
    const float* pw1_b    = (const float*)d_in[5];
    const float* dw2_w    = (const float*)d_in[6];
    const float* dw2_b    = (const float*)d_in[7];
    const float* pw2_w    = (const float*)d_in[8];
    const float* pw2_b    = (const float*)d_in[9];
    const float* dw3_w    = (const float*)d_in[10];
    const float* dw3_b    = (const float*)d_in[11];
    const float* pw3_w    = (const float*)d_in[12];
    const float* pw3_b    = (const float*)d_in[13];
    const float* fusion_w = (const float*)d_in[14];
    const float* fusion_b = (const float*)d_in[15];
    const float* bn_gamma = (const float*)d_in[16];
    const float* bn_beta  = (const float*)d_in[17];
    const float* bn_mean  = (const float*)d_in[18];
    const float* bn_var   = (const float*)d_in[19];
    const float* prelu_a  = (const float*)d_in[20];

    int write_mic = (out_size >= BB*OC*TT*FF + BB*CC*TT*FF) ? 1 : 0;

    setup_kernel<<<1, 256>>>(pw1_w, pw1_b, dw1_w, dw1_b,
                             pw2_w, pw2_b, dw2_w, dw2_b,
                             pw3_w, pw3_b, dw3_w, dw3_b,
                             fusion_w, fusion_b, bn_gamma, bn_beta,
                             bn_mean, bn_var);

    size_t kref_smem = (size_t)(TILE_ELEMS + HH*CC + HH) * sizeof(float);
    kref_kernel<<<BB*TT, NTHREADS, kref_smem>>>(x_ref);

    size_t main_smem = (size_t)(5*TILE_ELEMS + HH*CC + HH*HH + OC*OC
                                + HH + HH + OC + 8*132) * sizeof(float);
    cudaFuncSetAttribute(main_kernel, cudaFuncAttributeMaxDynamicSharedMemorySize,
                         (int)main_smem);
    main_kernel<<<BB*TT, NTHREADS, main_smem>>>(x_mic, x_ref, prelu_a,
                                                (float*)d_out, write_mic);
}

// round 4
// speedup vs baseline: 1.6888x; 1.6888x over previous
#include <cuda_runtime.h>

#define BB 2
#define CC 48
#define HH 48
#define TT 400
#define FF 129
#define WW 11
#define FPAD 136          // padded f-stride for 48-row tiles (floats)
#define SST 132           // S (scores, transposed) f-stride
#define OC 96
#define WFS 97            // fusion weight row stride (odd -> no tail conflicts)
#define WFOFF 8000        // offset of staged fusion weights inside S buffer
#define NT 256

// ---------------- device scratch ----------------
__device__ float g_w1f[HH*CC], g_b1f[HH];
__device__ float g_w2f[HH*HH], g_b2f[HH];
__device__ float g_w3f[HH*CC], g_b3f[HH];
__device__ float g_wff[OC*OC], g_bff[OC];
__device__ float g_kref[BB*HH*TT*SST];     // K_ref padded to stride 132 (st.128-able)

// ---------------- setup: fold dw into pw, BN into fusion ----------------
__global__ void setup_kernel(const float* __restrict__ pw1_w, const float* __restrict__ pw1_b,
                             const float* __restrict__ dw1_w, const float* __restrict__ dw1_b,
                             const float* __restrict__ pw2_w, const float* __restrict__ pw2_b,
                             const float* __restrict__ dw2_w, const float* __restrict__ dw2_b,
                             const float* __restrict__ pw3_w, const float* __restrict__ pw3_b,
                             const float* __restrict__ dw3_w, const float* __restrict__ dw3_b,
                             const float* __restrict__ fusion_w, const float* __restrict__ fusion_b,
                             const float* __restrict__ bn_gamma, const float* __restrict__ bn_beta,
                             const float* __restrict__ bn_mean, const float* __restrict__ bn_var)
{
    int tid = threadIdx.x;
    int lane = tid & 31, wid = tid >> 5;
    for (int i = tid; i < HH*CC; i += NT) {
        int c = i % CC;
        g_w1f[i] = pw1_w[i] * dw1_w[c];
        g_w2f[i] = pw2_w[i] * dw2_w[c];
        g_w3f[i] = pw3_w[i] * dw3_w[c];
    }
    for (int i = tid; i < OC*OC; i += NT) {
        int o = i / OC;
        float s = bn_gamma[o] * rsqrtf(bn_var[o] + 1e-5f);
        g_wff[i] = fusion_w[i] * s;
    }
    // bias folds: one warp per output row, shuffle reduce over c
    for (int o = wid; o < HH; o += 8) {
        float p1 = pw1_w[o*CC + lane] * dw1_b[lane];
        float p2 = pw2_w[o*CC + lane] * dw2_b[lane];
        float p3 = pw3_w[o*CC + lane] * dw3_b[lane];
        if (lane < 16) {
            p1 += pw1_w[o*CC + 32 + lane] * dw1_b[32 + lane];
            p2 += pw2_w[o*CC + 32 + lane] * dw2_b[32 + lane];
            p3 += pw3_w[o*CC + 32 + lane] * dw3_b[32 + lane];
        }
        #pragma unroll
        for (int off = 16; off; off >>= 1) {
            p1 += __shfl_down_sync(0xffffffffu, p1, off);
            p2 += __shfl_down_sync(0xffffffffu, p2, off);
            p3 += __shfl_down_sync(0xffffffffu, p3, off);
        }
        if (lane == 0) {
            g_b1f[o] = pw1_b[o] + p1;
            g_b2f[o] = pw2_b[o] + p2;
            g_b3f[o] = pw3_b[o] + p3;
        }
    }
    if (tid < OC) {
        float s = bn_gamma[tid] * rsqrtf(bn_var[tid] + 1e-5f);
        g_bff[tid] = (fusion_b[tid] - bn_mean[tid]) * s + bn_beta[tid];
    }
}

// ---------------- K_ref precompute (register-tiled) ----------------
__global__ __launch_bounds__(NT) void kref_kernel(const float* __restrict__ x_ref)
{
    __shared__ float xr[CC*FPAD];
    __shared__ float w3[HH*CC];
    __shared__ float b3[HH];

    int b = blockIdx.x / TT;
    int t = blockIdx.x % TT;
    int tid = threadIdx.x;
    int warp = tid >> 5, lane = tid & 31;

    for (int i = tid; i < CC*FF; i += NT) {
        int c = i / FF, f = i % FF;
        xr[c*FPAD + f] = x_ref[((b*CC + c)*TT + t)*FF + f];
    }
    for (int i = tid; i < HH*CC; i += NT) w3[i] = g_w3f[i];
    if (tid < HH) b3[tid] = g_b3f[tid];
    __syncthreads();

    // main: warp -> 6 h rows, lane -> 4 f
    {
        int h0 = 6 * warp;
        float acc[6][4];
        #pragma unroll
        for (int i = 0; i < 6; i++) {
            float bv = b3[h0 + i];
            acc[i][0] = bv; acc[i][1] = bv; acc[i][2] = bv; acc[i][3] = bv;
        }
        #pragma unroll 4
        for (int c = 0; c < CC; c++) {
            float4 xv = *(const float4*)(xr + c*FPAD + 4*lane);
            #pragma unroll
            for (int i = 0; i < 6; i++) {
                float wv = w3[(h0 + i)*CC + c];
                acc[i][0] += wv * xv.x; acc[i][1] += wv * xv.y;
                acc[i][2] += wv * xv.z; acc[i][3] += wv * xv.w;
            }
        }
        #pragma unroll
        for (int i = 0; i < 6; i++) {
            float4* dst = (float4*)(g_kref + (size_t)((b*HH + h0 + i)*TT + t)*SST + 4*lane);
            *dst = make_float4(acc[i][0], acc[i][1], acc[i][2], acc[i][3]);
        }
    }
    // tail: column f = 128
    if (tid < HH) {
        int h = tid;
        float acc = b3[h];
        #pragma unroll 8
        for (int c = 0; c < CC; c++) acc += w3[h*CC + c] * xr[c*FPAD + 128];
        g_kref[(size_t)((b*HH + h)*TT + t)*SST + 128] = acc;
    }
}

// ---------------- main fused kernel ----------------
__global__ __launch_bounds__(NT, 1) void main_kernel(const float* __restrict__ x_mic,
                                                     const float* __restrict__ x_ref,
                                                     const float* __restrict__ prelu_a,
                                                     float* __restrict__ out,
                                                     int write_mic)
{
    extern __shared__ float sm[];
    float* xm  = sm;                 // 48*136 : x_mic tile, later x_ref window slice
    float* Qs  = xm  + CC*FPAD;      // 48*136
    float* Ks  = Qs  + CC*FPAD;      // 48*136 : K, later kref window slice
    float* mic = Ks  + CC*FPAD;      // 48*136
    float* S   = mic + CC*FPAD;      // 132*132 : scores transposed; later refb + staged wf
    float* w1  = S   + SST*SST;      // 48*48
    float* w2  = w1  + HH*CC;        // 48*48
    float* b1  = w2  + HH*HH;        // 48
    float* b2  = b1  + HH;           // 48
    float* bf  = b2  + HH;           // 96

    int b = blockIdx.x / TT;
    int t = blockIdx.x % TT;
    int tid  = threadIdx.x;
    int warp = tid >> 5;
    int lane = tid & 31;

    // ---- loads (zero-pad f columns 129..135) ----
    for (int i = tid; i < CC*FPAD; i += NT) {
        int c = i / FPAD, f = i % FPAD;
        xm[i] = (f < FF) ? x_mic[((b*CC + c)*TT + t)*FF + f] : 0.f;
    }
    for (int i = tid; i < HH*CC; i += NT) { w1[i] = g_w1f[i]; w2[i] = g_w2f[i]; }
    if (tid < HH) { b1[tid] = g_b1f[tid]; b2[tid] = g_b2f[tid]; }
    if (tid < OC) bf[tid] = g_bff[tid];
    __syncthreads();

    // ---- Q = W1f @ xm + b1 ----
    {
        int h0 = 6 * warp;
        float acc[6][4];
        #pragma unroll
        for (int i = 0; i < 6; i++) {
            float bv = b1[h0 + i];
            acc[i][0] = bv; acc[i][1] = bv; acc[i][2] = bv; acc[i][3] = bv;
        }
        #pragma unroll 4
        for (int c = 0; c < CC; c++) {
            float4 xv = *(const float4*)(xm + c*FPAD + 4*lane);
            #pragma unroll
            for (int i = 0; i < 6; i++) {
                float wv = w1[(h0 + i)*CC + c];
                acc[i][0] += wv * xv.x; acc[i][1] += wv * xv.y;
                acc[i][2] += wv * xv.z; acc[i][3] += wv * xv.w;
            }
        }
        #pragma unroll
        for (int i = 0; i < 6; i++)
            *(float4*)(Qs + (h0 + i)*FPAD + 4*lane) =
                make_float4(acc[i][0], acc[i][1], acc[i][2], acc[i][3]);
    }
    if (tid < HH) {            // tail f = 128..135 (128 real; 129..135 finite)
        int h = tid;
        float acc[8];
        #pragma unroll
        for (int k = 0; k < 8; k++) acc[k] = b1[h];
        #pragma unroll 4
        for (int c = 0; c < CC; c++) {
            float wv = w1[h*CC + c];
            #pragma unroll
            for (int k = 0; k < 8; k++) acc[k] += wv * xm[c*FPAD + 128 + k];
        }
        #pragma unroll
        for (int k = 0; k < 8; k++) Qs[h*FPAD + 128 + k] = acc[k];
    }
    __syncthreads();

    // ---- K = W2f @ Q + b2 ----
    {
        int h0 = 6 * warp;
        float acc[6][4];
        #pragma unroll
        for (int i = 0; i < 6; i++) {
            float bv = b2[h0 + i];
            acc[i][0] = bv; acc[i][1] = bv; acc[i][2] = bv; acc[i][3] = bv;
        }
        #pragma unroll 4
        for (int c = 0; c < CC; c++) {
            float4 xv = *(const float4*)(Qs + c*FPAD + 4*lane);
            #pragma unroll
            for (int i = 0; i < 6; i++) {
                float wv = w2[(h0 + i)*CC + c];
                acc[i][0] += wv * xv.x; acc[i][1] += wv * xv.y;
                acc[i][2] += wv * xv.z; acc[i][3] += wv * xv.w;
            }
        }
        #pragma unroll
        for (int i = 0; i < 6; i++)
            *(float4*)(Ks + (h0 + i)*FPAD + 4*lane) =
                make_float4(acc[i][0], acc[i][1], acc[i][2], acc[i][3]);
    }
    if (tid < HH) {            // tail f = 128..131 (128 real; 129..131 finite)
        int h = tid;
        float acc[4];
        #pragma unroll
        for (int k = 0; k < 4; k++) acc[k] = b2[h];
        #pragma unroll 4
        for (int c = 0; c < CC; c++) {
            float wv = w2[h*CC + c];
            #pragma unroll
            for (int k = 0; k < 4; k++) acc[k] += wv * Qs[c*FPAD + 128 + k];
        }
        #pragma unroll
        for (int k = 0; k < 4; k++) Ks[h*FPAD + 128 + k] = acc[k];
    }
    __syncthreads();

    // ---- scores, stored transposed: S[g][f] = scale * sum_h Q[h][f] K[h][g] ----
    {
        const float scale = 0.144337567297406441f;  // 1/sqrt(48)
        for (int tile = tid; tile < 17*33; tile += NT) {
            int fi = tile % 17, gi = tile / 17;
            int f0 = fi * 8, g0 = gi * 4;
            float acc[4][8];
            #pragma unroll
            for (int j = 0; j < 4; j++)
                #pragma unroll
                for (int k = 0; k < 8; k++) acc[j][k] = 0.f;
            #pragma unroll 2
            for (int h = 0; h < HH; h++) {
                float4 qa = *(const float4*)(Qs + h*FPAD + f0);
                float4 qb = *(const float4*)(Qs + h*FPAD + f0 + 4);
                float4 kv = *(const float4*)(Ks + h*FPAD + g0);
                float kk[4] = {kv.x, kv.y, kv.z, kv.w};
                float qq[8] = {qa.x, qa.y, qa.z, qa.w, qb.x, qb.y, qb.z, qb.w};
                #pragma unroll
                for (int j = 0; j < 4; j++)
                    #pragma unroll
                    for (int k = 0; k < 8; k++) acc[j][k] += kk[j] * qq[k];
            }
            #pragma unroll
            for (int j = 0; j < 4; j++) {
                float* srow = S + (g0 + j)*SST + f0;
                *(float4*)(srow) = make_float4(acc[j][0]*scale, acc[j][1]*scale,
                                               acc[j][2]*scale, acc[j][3]*scale);
                if (fi != 16)
                    *(float4*)(srow + 4) = make_float4(acc[j][4]*scale, acc[j][5]*scale,
                                                       acc[j][6]*scale, acc[j][7]*scale);
            }
        }
    }
    __syncthreads();

    // ---- softmax over g (columns of S), per f < 129 ----
    if (tid < FF) {
        int f = tid;
        float m = -3.4e38f;
        #pragma unroll 4
        for (int g = 0; g < FF; g++) m = fmaxf(m, S[g*SST + f]);
        float sum = 0.f;
        #pragma unroll 4
        for (int g = 0; g < FF; g++) {
            float e = __expf(S[g*SST + f] - m);
            S[g*SST + f] = e;
            sum += e;
        }
        float inv = 1.f / sum;
        #pragma unroll 4
        for (int g = 0; g < FF; g++) S[g*SST + f] *= inv;
    }
    __syncthreads();

    // ---- mic_out[c][f] = sum_g S[g][f] * xm[c][g] ----
    {
        int c0 = 6 * warp;
        float acc[6][4];
        #pragma unroll
        for (int i = 0; i < 6; i++)
            acc[i][0] = acc[i][1] = acc[i][2] = acc[i][3] = 0.f;
        #pragma unroll 2
        for (int g = 0; g < FF; g++) {
            float4 sv = *(const float4*)(S + g*SST + 4*lane);
            #pragma unroll
            for (int i = 0; i < 6; i++) {
                float xv = xm[(c0 + i)*FPAD + g];
                acc[i][0] += xv * sv.x; acc[i][1] += xv * sv.y;
                acc[i][2] += xv * sv.z; acc[i][3] += xv * sv.w;
            }
        }
        #pragma unroll
        for (int i = 0; i < 6; i++)
            *(float4*)(mic + (c0 + i)*FPAD + 4*lane) =
                make_float4(acc[i][0], acc[i][1], acc[i][2], acc[i][3]);
    }
    if (tid < CC) {            // tail f = 128
        int c = tid;
        float acc = 0.f;
        #pragma unroll 4
        for (int g = 0; g < FF; g++) acc += S[g*SST + 128] * xm[c*FPAD + g];
        mic[c*FPAD + 128] = acc;
    }
    __syncthreads();

    // ---- windowed ref cross-attention, register accumulators ----
    float rr[6][4];
    float r4[6];
    #pragma unroll
    for (int i = 0; i < 6; i++) {
        rr[i][0] = rr[i][1] = rr[i][2] = rr[i][3] = 0.f;
        r4[i] = 0.f;
    }
    {
        int h0 = 6 * warp;
        int j0 = (t < WW - 1) ? (WW - 1 - t) : 0;
        for (int j = j0; j < WW; j++) {
            int tj = t + j - (WW - 1);
            __syncthreads();   // previous consumers of xm/Ks done
            for (int i = tid; i < CC*FF; i += NT) {
                int c = i / FF, f = i % FF;
                xm[c*FPAD + f] = x_ref[((b*CC + c)*TT + tj)*FF + f];
            }
            for (int i = tid; i < CC*33; i += NT) {
                int c = i / 33, m4 = i % 33;
                *(float4*)(Ks + c*FPAD + 4*m4) =
                    *(const float4*)(g_kref + (size_t)((b*HH + c)*TT + tj)*SST + 4*m4);
            }
            __syncthreads();
            #pragma unroll
            for (int i = 0; i < 6; i++) {
                const float* qr = Qs + (h0 + i)*FPAD;
                const float* kr = Ks + (h0 + i)*FPAD;
                const float* vr = xm + (h0 + i)*FPAD;
                float p0 = qr[lane]      * kr[lane];
                float p1 = qr[lane + 32] * kr[lane + 32];
                float p2 = qr[lane + 64] * kr[lane + 64];
                float p3 = qr[lane + 96] * kr[lane + 96];
                float p4 = qr[128]       * kr[128];
                float m = fmaxf(fmaxf(p0, p1), fmaxf(p2, p3));
                m = fmaxf(m, p4);
                #pragma unroll
                for (int o = 16; o; o >>= 1) m = fmaxf(m, __shfl_xor_sync(0xffffffffu, m, o));
                float e0 = __expf(p0 - m), e1 = __expf(p1 - m), e2 = __expf(p2 - m),
                      e3 = __expf(p3 - m), e4 = __expf(p4 - m);
                float ssum = e0 + e1 + e2 + e3 + (lane == 0 ? e4 : 0.f);
                #pragma unroll
                for (int o = 16; o; o >>= 1) ssum += __shfl_xor_sync(0xffffffffu, ssum, o);
                float inv = 1.f / ssum;
                rr[i][0] += vr[lane]      * e0 * inv;
                rr[i][1] += vr[lane + 32] * e1 * inv;
                rr[i][2] += vr[lane + 64] * e2 * inv;
                rr[i][3] += vr[lane + 96] * e3 * inv;
                r4[i]    += vr[128]       * e4 * inv;
            }
        }
    }
    __syncthreads();
    // spill ref accumulators into S region (dead) + stage fusion weights into S high half
    float* refb = S;
    float* wf   = S + WFOFF;
    {
        int h0 = 6 * warp;
        #pragma unroll
        for (int i = 0; i < 6; i++) {
            refb[(h0 + i)*FPAD + lane]      = rr[i][0];
            refb[(h0 + i)*FPAD + lane + 32] = rr[i][1];
            refb[(h0 + i)*FPAD + lane + 64] = rr[i][2];
            refb[(h0 + i)*FPAD + lane + 96] = rr[i][3];
            if (lane == 0) refb[(h0 + i)*FPAD + 128] = r4[i];
        }
    }
    for (int i = tid; i < OC*OC; i += NT) {
        int o = i / OC, c = i % OC;
        wf[o*WFS + c] = g_wff[i];
    }
    __syncthreads();

    // ---- fusion GEMM + PReLU + writes ----
    float aneg = prelu_a[0];
    {
        int o0 = 12 * warp;
        float acc[12][4];
        #pragma unroll
        for (int i = 0; i < 12; i++) {
            float bv = bf[o0 + i];
            acc[i][0] = bv; acc[i][1] = bv; acc[i][2] = bv; acc[i][3] = bv;
        }
        #pragma unroll 2
        for (int c = 0; c < CC; c++) {
            float4 mv = *(const float4*)(mic + c*FPAD + 4*lane);
            #pragma unroll
            for (int i = 0; i < 12; i++) {
                float wv = wf[(o0 + i)*WFS + c];
                acc[i][0] += wv * mv.x; acc[i][1] += wv * mv.y;
                acc[i][2] += wv * mv.z; acc[i][3] += wv * mv.w;
            }
        }
        #pragma unroll 2
        for (int c = 0; c < CC; c++) {
            float4 rv = *(const float4*)(refb + c*FPAD + 4*lane);
            #pragma unroll
            for (int i = 0; i < 12; i++) {
                float wv = wf[(o0 + i)*WFS + CC + c];
                acc[i][0] += wv * rv.x; acc[i][1] += wv * rv.y;
                acc[i][2] += wv * rv.z; acc[i][3] += wv * rv.w;
            }
        }
        #pragma unroll
        for (int i = 0; i < 12; i++) {
            float* orow = out + (size_t)((b*OC + o0 + i)*TT + t)*FF + 4*lane;
            #pragma unroll
            for (int k = 0; k < 4; k++) {
                float v = acc[i][k];
                orow[k] = (v >= 0.f) ? v : aneg * v;
            }
        }
    }
    if (tid < OC) {            // tail f = 128
        int o = tid;
        float acc = bf[o];
        #pragma unroll 4
        for (int c = 0; c < CC; c++) acc += wf[o*WFS + c] * mic[c*FPAD + 128];
        #pragma unroll 4
        for (int c = 0; c < CC; c++) acc += wf[o*WFS + CC + c] * refb[c*FPAD + 128];
        out[(size_t)((b*OC + o)*TT + t)*FF + 128] = (acc >= 0.f) ? acc : aneg * acc;
    }
    if (write_mic) {
        float* out2 = out + (size_t)BB*OC*TT*FF;
        for (int i = tid; i < CC*FF; i += NT) {
            int c = i / FF, f = i % FF;
            out2[((b*CC + c)*TT + t)*FF + f] = mic[c*FPAD + f];
        }
    }
}

// ---------------- launch ----------------
extern "C" void kernel_launch(void* const* d_in, const int* in_sizes, int n_in,
                              void* d_out, int out_size)
{
    const float* x_mic    = (const float*)d_in[0];
    const float* x_ref    = (const float*)d_in[1];
    const float* dw1_w    = (const float*)d_in[2];
    const float* dw1_b    = (const float*)d_in[3];
    const float* pw1_w    = (const float*)d_in[4];
    const float* pw1_b    = (const float*)d_in[5];
    const float* dw2_w    = (const float*)d_in[6];
    const float* dw2_b    = (const float*)d_in[7];
    const float* pw2_w    = (const float*)d_in[8];
    const float* pw2_b    = (const float*)d_in[9];
    const float* dw3_w    = (const float*)d_in[10];
    const float* dw3_b    = (const float*)d_in[11];
    const float* pw3_w    = (const float*)d_in[12];
    const float* pw3_b    = (const float*)d_in[13];
    const float* fusion_w = (const float*)d_in[14];
    const float* fusion_b = (const float*)d_in[15];
    const float* bn_gamma = (const float*)d_in[16];
    const float* bn_beta  = (const float*)d_in[17];
    const float* bn_mean  = (const float*)d_in[18];
    const float* bn_var   = (const float*)d_in[19];
    const float* prelu_a  = (const float*)d_in[20];

    int write_mic = (out_size >= BB*OC*TT*FF + BB*CC*TT*FF) ? 1 : 0;

    setup_kernel<<<1, NT>>>(pw1_w, pw1_b, dw1_w, dw1_b,
                            pw2_w, pw2_b, dw2_w, dw2_b,
                            pw3_w, pw3_b, dw3_w, dw3_b,
                            fusion_w, fusion_b, bn_gamma, bn_beta,
                            bn_mean, bn_var);

    kref_kernel<<<BB*TT, NT>>>(x_ref);

    size_t main_smem = (size_t)(4*CC*FPAD + SST*SST + 2*HH*CC
                                + HH + HH + OC) * sizeof(float);   // 193,344 B
    cudaFuncSetAttribute(main_kernel, cudaFuncAttributeMaxDynamicSharedMemorySize,
                         (int)main_smem);
    main_kernel<<<BB*TT, NT, main_smem>>>(x_mic, x_ref, prelu_a,
                                          (float*)d_out, write_mic);
}

// round 5
// speedup vs baseline: 2.6625x; 1.5766x over previous
#include <cuda_runtime.h>

#define BB 2
#define CC 48
#define HH 48
#define TT 400
#define FF 129
#define WW 11
#define FPAD 136          // padded f-stride for 48-row tiles (floats)
#define SST 132           // S f-stride (and padded gmem stride for kref/xrefp)
#define SROWS 136         // S rows (scores tiles write g up to 135)
#define OC 96
#define WFS 100           // fusion weight row stride (x4 -> 16B-aligned float4 rows)
#define NT 512
#define NTK 256

typedef unsigned long long u64;

__device__ __forceinline__ u64 pk2(float lo, float hi) {
    u64 r; asm("mov.b64 %0,{%1,%2};" : "=l"(r) : "f"(lo), "f"(hi)); return r;
}
__device__ __forceinline__ u64 bc2(float v) { return pk2(v, v); }
__device__ __forceinline__ void fma2(u64& d, u64 a, u64 b) {
    asm("fma.rn.f32x2 %0,%1,%2,%0;" : "+l"(d) : "l"(a), "l"(b));
}
__device__ __forceinline__ float2 up2(u64 v) {
    float2 r; asm("mov.b64 {%0,%1},%2;" : "=f"(r.x), "=f"(r.y) : "l"(v)); return r;
}
__device__ __forceinline__ void cpa16(float* dst, const float* src) {
    unsigned d = (unsigned)__cvta_generic_to_shared(dst);
    asm volatile("cp.async.ca.shared.global [%0], [%1], 16;" :: "r"(d), "l"(src));
}

// ---------------- device scratch ----------------
__device__ float g_w1f[HH*CC], g_b1f[HH];
__device__ float g_w2f[HH*HH], g_b2f[HH];   // scale 1/sqrt(48) folded in
__device__ float g_w3f[HH*CC], g_b3f[HH];
__device__ float g_wff[OC*OC], g_bff[OC];
__device__ float g_kref[(size_t)BB*HH*TT*SST];    // K_ref, stride-132 padded
__device__ float g_xrefp[(size_t)BB*CC*TT*SST];   // x_ref, stride-132 padded copy

// ---------------- setup: fold dw into pw, scale into K path, BN into fusion ----
__global__ void setup_kernel(const float* __restrict__ pw1_w, const float* __restrict__ pw1_b,
                             const float* __restrict__ dw1_w, const float* __restrict__ dw1_b,
                             const float* __restrict__ pw2_w, const float* __restrict__ pw2_b,
                             const float* __restrict__ dw2_w, const float* __restrict__ dw2_b,
                             const float* __restrict__ pw3_w, const float* __restrict__ pw3_b,
                             const float* __restrict__ dw3_w, const float* __restrict__ dw3_b,
                             const float* __restrict__ fusion_w, const float* __restrict__ fusion_b,
                             const float* __restrict__ bn_gamma, const float* __restrict__ bn_beta,
                             const float* __restrict__ bn_mean, const float* __restrict__ bn_var)
{
    const float SCALE = 0.144337567297406441f;  // 1/sqrt(48)
    int tid = threadIdx.x;
    int lane = tid & 31, wid = tid >> 5;
    for (int i = tid; i < HH*CC; i += NTK) {
        int c = i % CC;
        g_w1f[i] = pw1_w[i] * dw1_w[c];
        g_w2f[i] = pw2_w[i] * dw2_w[c] * SCALE;
        g_w3f[i] = pw3_w[i] * dw3_w[c];
    }
    for (int i = tid; i < OC*OC; i += NTK) {
        int o = i / OC;
        float s = bn_gamma[o] * rsqrtf(bn_var[o] + 1e-5f);
        g_wff[i] = fusion_w[i] * s;
    }
    for (int o = wid; o < HH; o += 8) {
        float p1 = pw1_w[o*CC + lane] * dw1_b[lane];
        float p2 = pw2_w[o*CC + lane] * dw2_b[lane];
        float p3 = pw3_w[o*CC + lane] * dw3_b[lane];
        if (lane < 16) {
            p1 += pw1_w[o*CC + 32 + lane] * dw1_b[32 + lane];
            p2 += pw2_w[o*CC + 32 + lane] * dw2_b[32 + lane];
            p3 += pw3_w[o*CC + 32 + lane] * dw3_b[32 + lane];
        }
        #pragma unroll
        for (int off = 16; off; off >>= 1) {
            p1 += __shfl_down_sync(0xffffffffu, p1, off);
            p2 += __shfl_down_sync(0xffffffffu, p2, off);
            p3 += __shfl_down_sync(0xffffffffu, p3, off);
        }
        if (lane == 0) {
            g_b1f[o] = pw1_b[o] + p1;
            g_b2f[o] = (pw2_b[o] + p2) * SCALE;
            g_b3f[o] = pw3_b[o] + p3;
        }
    }
    if (tid < OC) {
        float s = bn_gamma[tid] * rsqrtf(bn_var[tid] + 1e-5f);
        g_bff[tid] = (fusion_b[tid] - bn_mean[tid]) * s + bn_beta[tid];
    }
}

// ---------------- K_ref precompute + padded x_ref copy ----------------
__global__ __launch_bounds__(NTK) void kref_kernel(const float* __restrict__ x_ref)
{
    __shared__ float xr[CC*FPAD];
    __shared__ float w3[HH*CC];
    __shared__ float b3[HH];

    int b = blockIdx.x / TT;
    int t = blockIdx.x % TT;
    int tid = threadIdx.x;
    int warp = tid >> 5, lane = tid & 31;

    for (int i = tid; i < CC*FPAD; i += NTK) {
        int c = i / FPAD, f = i % FPAD;
        xr[i] = (f < FF) ? x_ref[((b*CC + c)*TT + t)*FF + f] : 0.f;
    }
    for (int i = tid; i < HH*CC; i += NTK) w3[i] = g_w3f[i];
    if (tid < HH) b3[tid] = g_b3f[tid];
    __syncthreads();

    // padded x_ref copy (cols 0..131, 129..131 zero)
    for (int i = tid; i < CC*33; i += NTK) {
        int c = i / 33, m = i % 33;
        *(float4*)(g_xrefp + ((size_t)(b*CC + c)*TT + t)*SST + 4*m) =
            *(const float4*)(xr + c*FPAD + 4*m);
    }

    // K_ref GEMM: warp -> 6 rows, f32x2
    {
        int h0 = 6*warp;
        u64 acc[6][2];
        #pragma unroll
        for (int i = 0; i < 6; i++) acc[i][0] = acc[i][1] = bc2(b3[h0 + i]);
        #pragma unroll 2
        for (int c = 0; c < CC; c++) {
            ulonglong2 xv = *(const ulonglong2*)(xr + c*FPAD + 4*lane);
            #pragma unroll
            for (int i = 0; i < 6; i++) {
                u64 w = bc2(w3[(h0 + i)*CC + c]);
                fma2(acc[i][0], w, xv.x); fma2(acc[i][1], w, xv.y);
            }
        }
        #pragma unroll
        for (int i = 0; i < 6; i++) {
            float2 a = up2(acc[i][0]), c2 = up2(acc[i][1]);
            *(float4*)(g_kref + ((size_t)(b*HH + h0 + i)*TT + t)*SST + 4*lane) =
                make_float4(a.x, a.y, c2.x, c2.y);
        }
    }
    if (tid < HH) {   // col 128
        int h = tid;
        float acc = b3[h];
        #pragma unroll 8
        for (int c = 0; c < CC; c++) acc += w3[h*CC + c] * xr[c*FPAD + 128];
        g_kref[((size_t)(b*HH + h)*TT + t)*SST + 128] = acc;
    }
}

// ---------------- main fused kernel ----------------
__global__ __launch_bounds__(NT, 1) void main_kernel(const float* __restrict__ x_mic,
                                                     const float* __restrict__ prelu_a,
                                                     float* __restrict__ out,
                                                     int write_mic)
{
    extern __shared__ float sm[];
    float* xm  = sm;                  // 48*136
    float* Qs  = xm  + CC*FPAD;       // 48*136
    float* Ks  = Qs  + CC*FPAD;       // 48*136 ; window bufK[0]; later refb
    float* mic = Ks  + CC*FPAD;       // 48*136
    float* S   = mic + CC*FPAD;       // 136*132 ; window bufX[1]/bufK[1]; later wf
    float* w1  = S   + SROWS*SST;     // 48*48
    float* w2  = w1  + HH*CC;         // 48*48
    float* b1  = w2  + HH*HH;
    float* b2  = b1  + HH;
    float* bf  = b2  + HH;

    int b = blockIdx.x / TT;
    int t = blockIdx.x % TT;
    int tid  = threadIdx.x;
    int warp = tid >> 5;
    int lane = tid & 31;

    // ---- loads ----
    for (int i = tid; i < CC*FPAD; i += NT) {
        int c = i / FPAD, f = i % FPAD;
        xm[i] = (f < FF) ? x_mic[((b*CC + c)*TT + t)*FF + f] : 0.f;
    }
    for (int i = tid; i < HH*CC; i += NT) { w1[i] = g_w1f[i]; w2[i] = g_w2f[i]; }
    if (tid < HH) { b1[tid] = g_b1f[tid]; b2[tid] = g_b2f[tid]; }
    if (tid < OC) bf[tid] = g_bff[tid];
    __syncthreads();

    // ---- Q = W1f @ xm + b1  (warp -> 3 rows, f32x2) ----
    {
        int h0 = 3*warp;
        u64 acc[3][2];
        #pragma unroll
        for (int i = 0; i < 3; i++) acc[i][0] = acc[i][1] = bc2(b1[h0 + i]);
        #pragma unroll 2
        for (int c = 0; c < CC; c++) {
            ulonglong2 xv = *(const ulonglong2*)(xm + c*FPAD + 4*lane);
            #pragma unroll
            for (int i = 0; i < 3; i++) {
                u64 w = bc2(w1[(h0 + i)*CC + c]);
                fma2(acc[i][0], w, xv.x); fma2(acc[i][1], w, xv.y);
            }
        }
        #pragma unroll
        for (int i = 0; i < 3; i++) {
            float2 a = up2(acc[i][0]), c2 = up2(acc[i][1]);
            *(float4*)(Qs + (h0 + i)*FPAD + 4*lane) = make_float4(a.x, a.y, c2.x, c2.y);
        }
    }
    if (tid < HH) {      // cols 128..135
        int h = tid;
        float acc[8];
        #pragma unroll
        for (int k = 0; k < 8; k++) acc[k] = b1[h];
        #pragma unroll 4
        for (int c = 0; c < CC; c++) {
            float wv = w1[h*CC + c];
            #pragma unroll
            for (int k = 0; k < 8; k++) acc[k] += wv * xm[c*FPAD + 128 + k];
        }
        #pragma unroll
        for (int k = 0; k < 8; k++) Qs[h*FPAD + 128 + k] = acc[k];
    }
    __syncthreads();

    // ---- K = W2f @ Q + b2  (scale folded) ----
    {
        int h0 = 3*warp;
        u64 acc[3][2];
        #pragma unroll
        for (int i = 0; i < 3; i++) acc[i][0] = acc[i][1] = bc2(b2[h0 + i]);
        #pragma unroll 2
        for (int c = 0; c < CC; c++) {
            ulonglong2 xv = *(const ulonglong2*)(Qs + c*FPAD + 4*lane);
            #pragma unroll
            for (int i = 0; i < 3; i++) {
                u64 w = bc2(w2[(h0 + i)*CC + c]);
                fma2(acc[i][0], w, xv.x); fma2(acc[i][1], w, xv.y);
            }
        }
        #pragma unroll
        for (int i = 0; i < 3; i++) {
            float2 a = up2(acc[i][0]), c2 = up2(acc[i][1]);
            *(float4*)(Ks + (h0 + i)*FPAD + 4*lane) = make_float4(a.x, a.y, c2.x, c2.y);
        }
    }
    if (tid < HH) {      // cols 128..135
        int h = tid;
        float acc[8];
        #pragma unroll
        for (int k = 0; k < 8; k++) acc[k] = b2[h];
        #pragma unroll 4
        for (int c = 0; c < CC; c++) {
            float wv = w2[h*CC + c];
            #pragma unroll
            for (int k = 0; k < 8; k++) acc[k] += wv * Qs[c*FPAD + 128 + k];
        }
        #pragma unroll
        for (int k = 0; k < 8; k++) Ks[h*FPAD + 128 + k] = acc[k];
    }
    __syncthreads();

    // ---- scores transposed: S[g][f] = sum_h K[h][g] * Q[h][f]  (8g x 8f tiles) ----
    if (tid < 17*17) {
        int fi = tid % 17, gi = tid / 17;
        int f0 = fi*8, g0 = gi*8;
        u64 acc[8][4];
        #pragma unroll
        for (int j = 0; j < 8; j++)
            #pragma unroll
            for (int k = 0; k < 4; k++) acc[j][k] = 0ull;
        #pragma unroll 2
        for (int h = 0; h < HH; h++) {
            ulonglong2 qa = *(const ulonglong2*)(Qs + h*FPAD + f0);
            ulonglong2 qb = *(const ulonglong2*)(Qs + h*FPAD + f0 + 4);
            ulonglong2 ka = *(const ulonglong2*)(Ks + h*FPAD + g0);
            ulonglong2 kb = *(const ulonglong2*)(Ks + h*FPAD + g0 + 4);
            float2 k01 = up2(ka.x), k23 = up2(ka.y), k45 = up2(kb.x), k67 = up2(kb.y);
            float kk[8] = {k01.x, k01.y, k23.x, k23.y, k45.x, k45.y, k67.x, k67.y};
            #pragma unroll
            for (int j = 0; j < 8; j++) {
                u64 kb2 = bc2(kk[j]);
                fma2(acc[j][0], kb2, qa.x); fma2(acc[j][1], kb2, qa.y);
                fma2(acc[j][2], kb2, qb.x); fma2(acc[j][3], kb2, qb.y);
            }
        }
        #pragma unroll
        for (int j = 0; j < 8; j++) {
            float* srow = S + (g0 + j)*SST + f0;
            float2 a0 = up2(acc[j][0]), a1 = up2(acc[j][1]);
            *(float4*)srow = make_float4(a0.x, a0.y, a1.x, a1.y);
            if (fi < 16) {
                float2 a2 = up2(acc[j][2]), a3 = up2(acc[j][3]);
                *(float4*)(srow + 4) = make_float4(a2.x, a2.y, a3.x, a3.y);
            }
        }
    }
    __syncthreads();

    // ---- softmax over g (columns of S), per f < 129 ----
    if (tid < FF) {
        int f = tid;
        float m = -3.4e38f;
        #pragma unroll 4
        for (int g = 0; g < FF; g++) m = fmaxf(m, S[g*SST + f]);
        float sum = 0.f;
        #pragma unroll 4
        for (int g = 0; g < FF; g++) {
            float e = __expf(S[g*SST + f] - m);
            S[g*SST + f] = e;
            sum += e;
        }
        float inv = 1.f / sum;
        #pragma unroll 4
        for (int g = 0; g < FF; g++) S[g*SST + f] *= inv;
    }
    __syncthreads();

    // ---- mic_out[c][f] = sum_g S[g][f] * xm[c][g]  (warp -> 3 rows, f32x2) ----
    {
        int c0 = 3*warp;
        u64 acc[3][2] = {{0ull,0ull},{0ull,0ull},{0ull,0ull}};
        for (int g4 = 0; g4 < 32; g4++) {
            int g0 = 4*g4;
            float4 x0 = *(const float4*)(xm + (c0+0)*FPAD + g0);
            float4 x1 = *(const float4*)(xm + (c0+1)*FPAD + g0);
            float4 x2 = *(const float4*)(xm + (c0+2)*FPAD + g0);
            float xa0[4] = {x0.x, x0.y, x0.z, x0.w};
            float xa1[4] = {x1.x, x1.y, x1.z, x1.w};
            float xa2[4] = {x2.x, x2.y, x2.z, x2.w};
            #pragma unroll
            for (int gg = 0; gg < 4; gg++) {
                ulonglong2 sv = *(const ulonglong2*)(S + (g0 + gg)*SST + 4*lane);
                u64 b0 = bc2(xa0[gg]); fma2(acc[0][0], b0, sv.x); fma2(acc[0][1], b0, sv.y);
                u64 bb1 = bc2(xa1[gg]); fma2(acc[1][0], bb1, sv.x); fma2(acc[1][1], bb1, sv.y);
                u64 bb2 = bc2(xa2[gg]); fma2(acc[2][0], bb2, sv.x); fma2(acc[2][1], bb2, sv.y);
            }
        }
        {   // g = 128
            ulonglong2 sv = *(const ulonglong2*)(S + 128*SST + 4*lane);
            #pragma unroll
            for (int i = 0; i < 3; i++) {
                u64 bx = bc2(xm[(c0+i)*FPAD + 128]);
                fma2(acc[i][0], bx, sv.x); fma2(acc[i][1], bx, sv.y);
            }
        }
        #pragma unroll
        for (int i = 0; i < 3; i++) {
            float2 a = up2(acc[i][0]), c2 = up2(acc[i][1]);
            *(float4*)(mic + (c0 + i)*FPAD + 4*lane) = make_float4(a.x, a.y, c2.x, c2.y);
        }
    }
    if (tid < CC) {      // col 128
        int c = tid;
        float acc = 0.f;
        #pragma unroll 4
        for (int g = 0; g < FF; g++) acc += S[g*SST + 128] * xm[c*FPAD + g];
        mic[c*FPAD + 128] = acc;
    }
    __syncthreads();

    // ---- windowed ref cross-attention: cp.async double-buffered pipeline ----
    float* bufX[2] = {xm, S};
    float* bufK[2] = {Ks, S + CC*FPAD};
    int h0w = 3*warp;
    float qv[3][5];
    #pragma unroll
    for (int i = 0; i < 3; i++) {
        const float* qr = Qs + (h0w + i)*FPAD;
        qv[i][0] = qr[lane]; qv[i][1] = qr[lane+32]; qv[i][2] = qr[lane+64];
        qv[i][3] = qr[lane+96]; qv[i][4] = qr[128];
    }
    float rr[3][4], r4[3];
    #pragma unroll
    for (int i = 0; i < 3; i++) { rr[i][0]=rr[i][1]=rr[i][2]=rr[i][3]=0.f; r4[i]=0.f; }

    int j0 = (t < WW - 1) ? (WW - 1 - t) : 0;
    // preload j0
    {
        int tj = t + j0 - (WW - 1);
        float* xd = bufX[j0 & 1]; float* kd = bufK[j0 & 1];
        for (int i = tid; i < CC*33; i += NT) {
            int c = i / 33, m = i % 33;
            size_t o = ((size_t)(b*CC + c)*TT + tj)*SST + 4*m;
            cpa16(xd + c*FPAD + 4*m, g_xrefp + o);
            cpa16(kd + c*FPAD + 4*m, g_kref + o);
        }
        asm volatile("cp.async.commit_group;");
    }
    for (int j = j0; j < WW; j++) {
        if (j + 1 < WW) {
            int tj = t + j + 1 - (WW - 1);
            float* xd = bufX[(j+1) & 1]; float* kd = bufK[(j+1) & 1];
            for (int i = tid; i < CC*33; i += NT) {
                int c = i / 33, m = i % 33;
                size_t o = ((size_t)(b*CC + c)*TT + tj)*SST + 4*m;
                cpa16(xd + c*FPAD + 4*m, g_xrefp + o);
                cpa16(kd + c*FPAD + 4*m, g_kref + o);
            }
            asm volatile("cp.async.commit_group;");
            asm volatile("cp.async.wait_group 1;");
        } else {
            asm volatile("cp.async.wait_group 0;");
        }
        __syncthreads();
        const float* cx = bufX[j & 1];
        const float* ck = bufK[j & 1];
        #pragma unroll
        for (int i = 0; i < 3; i++) {
            const float* kr = ck + (h0w + i)*FPAD;
            const float* vr = cx + (h0w + i)*FPAD;
            float p0 = qv[i][0] * kr[lane];
            float p1 = qv[i][1] * kr[lane + 32];
            float p2 = qv[i][2] * kr[lane + 64];
            float p3 = qv[i][3] * kr[lane + 96];
            float p4 = qv[i][4] * kr[128];
            float m = fmaxf(fmaxf(p0, p1), fmaxf(p2, p3));
            m = fmaxf(m, p4);
            #pragma unroll
            for (int o = 16; o; o >>= 1) m = fmaxf(m, __shfl_xor_sync(0xffffffffu, m, o));
            float e0 = __expf(p0 - m), e1 = __expf(p1 - m), e2 = __expf(p2 - m),
                  e3 = __expf(p3 - m), e4 = __expf(p4 - m);
            float ssum = e0 + e1 + e2 + e3 + (lane == 0 ? e4 : 0.f);
            #pragma unroll
            for (int o = 16; o; o >>= 1) ssum += __shfl_xor_sync(0xffffffffu, ssum, o);
            float inv = 1.f / ssum;
            rr[i][0] += vr[lane]      * e0 * inv;
            rr[i][1] += vr[lane + 32] * e1 * inv;
            rr[i][2] += vr[lane + 64] * e2 * inv;
            rr[i][3] += vr[lane + 96] * e3 * inv;
            r4[i]    += vr[128]       * e4 * inv;
        }
        __syncthreads();
    }

    // spill refb into Ks (dead); stage fusion weights into S (dead)
    float* refb = Ks;
    float* wf = S;
    #pragma unroll
    for (int i = 0; i < 3; i++) {
        float* row = refb + (h0w + i)*FPAD;
        row[lane]      = rr[i][0];
        row[lane + 32] = rr[i][1];
        row[lane + 64] = rr[i][2];
        row[lane + 96] = rr[i][3];
        if (lane == 0) row[128] = r4[i];
    }
    for (int i = tid; i < OC*OC; i += NT) {
        int o = i / OC, c = i % OC;
        wf[o*WFS + c] = g_wff[i];
    }
    __syncthreads();

    // ---- fusion GEMM + PReLU  (warp -> 6 rows, f32x2) ----
    float aneg = prelu_a[0];
    {
        int o0 = 6*warp;
        u64 acc[6][2];
        #pragma unroll
        for (int i = 0; i < 6; i++) acc[i][0] = acc[i][1] = bc2(bf[o0 + i]);
        #pragma unroll
        for (int half = 0; half < 2; half++) {
            const float* src = half ? refb : mic;
            int coff = half ? CC : 0;
            for (int c4 = 0; c4 < 12; c4++) {
                int c0 = 4*c4;
                float wv[6][4];
                #pragma unroll
                for (int i = 0; i < 6; i++) {
                    float4 w4 = *(const float4*)(wf + (o0 + i)*WFS + coff + c0);
                    wv[i][0] = w4.x; wv[i][1] = w4.y; wv[i][2] = w4.z; wv[i][3] = w4.w;
                }
                #pragma unroll
                for (int cc = 0; cc < 4; cc++) {
                    ulonglong2 mv = *(const ulonglong2*)(src + (c0 + cc)*FPAD + 4*lane);
                    #pragma unroll
                    for (int i = 0; i < 6; i++) {
                        u64 wb = bc2(wv[i][cc]);
                        fma2(acc[i][0], wb, mv.x); fma2(acc[i][1], wb, mv.y);
                    }
                }
            }
        }
        #pragma unroll
        for (int i = 0; i < 6; i++) {
            float2 a = up2(acc[i][0]), c2 = up2(acc[i][1]);
            float v[4] = {a.x, a.y, c2.x, c2.y};
            float* orow = out + (size_t)((b*OC + o0 + i)*TT + t)*FF + 4*lane;
            #pragma unroll
            for (int k = 0; k < 4; k++)
                orow[k] = (v[k] >= 0.f) ? v[k] : aneg * v[k];
        }
    }
    if (tid < OC) {      // col 128
        int o = tid;
        float acc = bf[o];
        #pragma unroll 4
        for (int c = 0; c < CC; c++) acc += wf[o*WFS + c] * mic[c*FPAD + 128];
        #pragma unroll 4
        for (int c = 0; c < CC; c++) acc += wf[o*WFS + CC + c] * refb[c*FPAD + 128];
        out[(size_t)((b*OC + o)*TT + t)*FF + 128] = (acc >= 0.f) ? acc : aneg * acc;
    }
    if (write_mic) {
        float* out2 = out + (size_t)BB*OC*TT*FF;
        for (int i = tid; i < CC*FF; i += NT) {
            int c = i / FF, f = i % FF;
            out2[((b*CC + c)*TT + t)*FF + f] = mic[c*FPAD + f];
        }
    }
}

// ---------------- launch ----------------
extern "C" void kernel_launch(void* const* d_in, const int* in_sizes, int n_in,
                              void* d_out, int out_size)
{
    const float* x_mic    = (const float*)d_in[0];
    const float* x_ref    = (const float*)d_in[1];
    const float* dw1_w    = (const float*)d_in[2];
    const float* dw1_b    = (const float*)d_in[3];
    const float* pw1_w    = (const float*)d_in[4];
    const float* pw1_b    = (const float*)d_in[5];
    const float* dw2_w    = (const float*)d_in[6];
    const float* dw2_b    = (const float*)d_in[7];
    const float* pw2_w    = (const float*)d_in[8];
    const float* pw2_b    = (const float*)d_in[9];
    const float* dw3_w    = (const float*)d_in[10];
    const float* dw3_b    = (const float*)d_in[11];
    const float* pw3_w    = (const float*)d_in[12];
    const float* pw3_b    = (const float*)d_in[13];
    const float* fusion_w = (const float*)d_in[14];
    const float* fusion_b = (const float*)d_in[15];
    const float* bn_gamma = (const float*)d_in[16];
    const float* bn_beta  = (const float*)d_in[17];
    const float* bn_mean  = (const float*)d_in[18];
    const float* bn_var   = (const float*)d_in[19];
    const float* prelu_a  = (const float*)d_in[20];

    int write_mic = (out_size >= BB*OC*TT*FF + BB*CC*TT*FF) ? 1 : 0;

    setup_kernel<<<1, NTK>>>(pw1_w, pw1_b, dw1_w, dw1_b,
                             pw2_w, pw2_b, dw2_w, dw2_b,
                             pw3_w, pw3_b, dw3_w, dw3_b,
                             fusion_w, fusion_b, bn_gamma, bn_beta,
                             bn_mean, bn_var);

    kref_kernel<<<BB*TT, NTK>>>(x_ref);

    size_t main_smem = (size_t)(4*CC*FPAD + SROWS*SST + 2*HH*CC
                                + HH + HH + OC) * sizeof(float);   // 195,456 B
    cudaFuncSetAttribute(main_kernel, cudaFuncAttributeMaxDynamicSharedMemorySize,
                         (int)main_smem);
    main_kernel<<<BB*TT, NT, main_smem>>>(x_mic, prelu_a, (float*)d_out, write_mic);
}